// round 14
// baseline (speedup 1.0000x reference)
#include <cuda_runtime.h>
#include <math.h>

#define NN 10000
#define EE 160000
#define BB 64
#define HH 64
#define EPSN 1e-9f
#define SQ3 1.7320508f
#define INV_AVG 0.0625f   // 1/16

#define TPTS 8192
#define NGRID 592          // 4*148 blocks for grid-stride node kernels
#define NBGRID 296         // 2/SM for fused nodeB
#define WS 68              // transposed 64-row weight stride (floats)
#define WS1 132            // transposed 128-row weight stride (floats)

// ---------------- scratch (static device globals; no allocation) -----------
__device__ float g_h[NN*HH];
__device__ float g_nfup0[NN*HH];
__device__ float g_sc[NN*HH];
__device__ float g_v3[NN*3*HH];
__device__ float g_agg[NN*4*HH];
__device__ float g_pos[NN*3];
__device__ float g_bsum[BB*3];
__device__ float g_bcnt[BB];
__device__ float g_tab[TPTS*HH];
__device__ float4 g_edat[EE];
__device__ int   g_cnt[NN];         // zeroed by k_scan after use (self-cleaning)
__device__ int   g_row[NN+1];
__device__ int   g_cur[NN];
__device__ int   g_eid[EE];
__device__ unsigned g_lmax_bits;

__device__ __forceinline__ float siluf(float x){
    float e = __expf(-x);
    return __fdividef(x, 1.f + e);
}

__device__ __forceinline__ float get_lm(){
    return fmaxf(__uint_as_float(g_lmax_bits), 1e-3f) * 1.0001f;
}

// transpose-load a 64x64 weight into padded smem: dst[j*WS + k] = W[k*64 + j]
__device__ __forceinline__ void load_wT(float* dst, const float* __restrict__ W, int tid){
    for (int x = tid; x < 4096; x += 256){
        int k = x >> 6, j = x & 63;
        dst[j*WS + k] = W[x];
    }
}

// ---------------- device helper: per-edge geometry + lmax reduce -----------
__device__ __forceinline__ void geom_block(int gb, const int* __restrict__ snd,
                                           const int* __restrict__ rcv,
                                           const float* __restrict__ shifts){
    __shared__ float s_max[256];
    int e = gb*256 + threadIdx.x;
    float len = 0.f;
    if (e < EE){
        int s = snd[e], r = rcv[e];
        float dx = g_pos[r*3+0] - g_pos[s*3+0] + shifts[e*3+0];
        float dy = g_pos[r*3+1] - g_pos[s*3+1] + shifts[e*3+1];
        float dz = g_pos[r*3+2] - g_pos[s*3+2] + shifts[e*3+2];
        len = sqrtf(dx*dx + dy*dy + dz*dz);
        float inv = SQ3 / (len + EPSN);
        g_edat[e] = make_float4(dx*inv, dy*inv, dz*inv, len);
    }
    int tid = threadIdx.x;
    s_max[tid] = len;
    __syncthreads();
    for (int off = 128; off > 0; off >>= 1){
        if (tid < off) s_max[tid] = fmaxf(s_max[tid], s_max[tid + off]);
        __syncthreads();
    }
    if (tid == 0) atomicMax(&g_lmax_bits, __float_as_uint(s_max[0]));
}

// ---------------- device helper: grid-stride table build (WT in smem) ------
__device__ __forceinline__ void table_gs(int bid, const float* __restrict__ Wr1,
                                         const float* __restrict__ br1,
                                         const float* __restrict__ Wr2){
    __shared__ __align__(16) float sWT[64*WS];
    __shared__ __align__(16) float sv[4][64];
    __shared__ float w1[64], b1[64];
    int tid = threadIdx.x;
    int j = tid & 63, slot = tid >> 6;
    load_wT(sWT, Wr2, tid);
    if (tid < 64){ w1[tid] = Wr1[tid]; b1[tid] = br1[tid]; }
    float dt = get_lm() / (float)TPTS;
    __syncthreads();
    const float4* wr = (const float4*)&sWT[j*WS];
    for (int pb = bid*4; pb < TPTS; pb += NGRID*4){
        int p = pb + slot;
        float lp = (float)p * dt;
        sv[slot][j] = siluf(lp * w1[j] + b1[j]);
        __syncthreads();
        float acc = 0.f;
        const float4* v4 = (const float4*)sv[slot];
        #pragma unroll
        for (int q = 0; q < 16; q++){
            float4 v = v4[q];
            float4 w = wr[q];
            acc = fmaf(v.x, w.x, acc);
            acc = fmaf(v.y, w.y, acc);
            acc = fmaf(v.z, w.z, acc);
            acc = fmaf(v.w, w.w, acc);
        }
        g_tab[p*64 + j] = acc * INV_AVG;
        __syncthreads();
    }
}

// ---------------- device helper: msgprep (nfup0 = src @ W_up) --------------
__device__ __forceinline__ void msgprep_block(int bid, const float* __restrict__ Wup,
                                              const float* __restrict__ src){
    __shared__ __align__(16) float sWT[64*WS];
    __shared__ __align__(16) float srow[4][64];
    int tid = threadIdx.x;
    int j = tid & 63, slot = tid >> 6;
    load_wT(sWT, Wup, tid);
    __syncthreads();
    const float4* wr = (const float4*)&sWT[j*WS];
    for (int base = bid*4; base < NN; base += NGRID*4){
        int n = base + slot;
        srow[slot][j] = src[n*64 + j];
        __syncthreads();
        float acc = 0.f;
        const float4* r4 = (const float4*)srow[slot];
        #pragma unroll
        for (int q = 0; q < 16; q++){
            float4 v = r4[q];
            float4 w = wr[q];
            acc = fmaf(v.x, w.x, acc);
            acc = fmaf(v.y, w.y, acc);
            acc = fmaf(v.z, w.z, acc);
            acc = fmaf(v.w, w.w, acc);
        }
        g_nfup0[n*64 + j] = acc;
        __syncthreads();
    }
}

// ---------------- init + hist merged ---------------------------------------
__global__ void k_inithist(const float* __restrict__ positions,
                           const int* __restrict__ rcv){
    if (blockIdx.x < 118){
        int i = blockIdx.x*256 + threadIdx.x;
        if (i < NN*3) g_pos[i] = positions[i];
        if (i < BB*3) g_bsum[i] = 0.f;
        if (i < BB)   g_bcnt[i] = 0.f;
        if (i == 0)   g_lmax_bits = 0u;
    } else {
        int e = (blockIdx.x - 118)*256 + threadIdx.x;
        if (e < EE) atomicAdd(&g_cnt[rcv[e]], 1);
    }
}

// scan consumes g_cnt and re-zeroes it for the next launch (graph replay).
__global__ void k_scan(){   // single block, 1024 threads
    __shared__ int s_part[1024];
    int tid = threadIdx.x;
    const int CH = (NN + 1023) / 1024;    // 10
    int base = tid * CH;
    int cnts[CH];
    int sum = 0;
    #pragma unroll
    for (int k = 0; k < CH; k++){
        int i = base + k;
        if (i < NN){
            cnts[k] = g_cnt[i];
            g_cnt[i] = 0;
            sum += cnts[k];
        } else cnts[k] = 0;
    }
    s_part[tid] = sum;
    __syncthreads();
    for (int off = 1; off < 1024; off <<= 1){
        int v = s_part[tid];
        int add = (tid >= off) ? s_part[tid - off] : 0;
        __syncthreads();
        s_part[tid] = v + add;
        __syncthreads();
    }
    int excl = (tid == 0) ? 0 : s_part[tid - 1];
    #pragma unroll
    for (int k = 0; k < CH; k++){
        int i = base + k;
        if (i < NN){
            g_row[i] = excl;
            g_cur[i] = excl;
            excl += cnts[k];
        }
    }
    if (tid == 1023) g_row[NN] = EE;
}

// ---------------- fill + embed + layer-0 geometry, merged ------------------
__global__ void k_fillembed(const int* __restrict__ snd, const int* __restrict__ rcv,
                            const float* __restrict__ shifts,
                            const float* __restrict__ node_attrs,
                            const float* __restrict__ t,
                            const int* __restrict__ batch,
                            const float* __restrict__ W_emb,
                            const float* __restrict__ b_emb){
    if (blockIdx.x < 625){
        int e = blockIdx.x*256 + threadIdx.x;
        if (e < EE){
            int pos = atomicAdd(&g_cur[rcv[e]], 1);
            g_eid[pos] = e;
        }
    } else if (blockIdx.x < 3125){
        int idx = (blockIdx.x - 625)*256 + threadIdx.x;
        if (idx >= NN*HH) return;
        int n = idx >> 6, j = idx & 63;
        float acc = b_emb[j];
        #pragma unroll
        for (int f = 0; f < 10; f++)
            acc += (node_attrs[n*10 + f] * 0.25f) * W_emb[f*64 + j];
        acc += t[batch[n]] * W_emb[10*64 + j];
        g_h[idx] = acc;
    } else {
        geom_block(blockIdx.x - 3125, snd, rcv, shifts);
    }
}

// ---------------- layer-0: table(gs) + msgprep merged ----------------------
__global__ __launch_bounds__(256)
void k_tabprep0(const float* __restrict__ Wr1, const float* __restrict__ br1,
                const float* __restrict__ Wr2, const float* __restrict__ Wup){
    if (blockIdx.x < NGRID) table_gs(blockIdx.x, Wr1, br1, Wr2);
    else                    msgprep_block(blockIdx.x - NGRID, Wup, g_h);
}

// ---------------- layer-1: geom + msgprep merged (src = g_sc) --------------
__global__ __launch_bounds__(256)
void k_geomprep(const int* __restrict__ snd, const int* __restrict__ rcv,
                const float* __restrict__ shifts, const float* __restrict__ Wup){
    if (blockIdx.x < 625) geom_block(blockIdx.x, snd, rcv, shifts);
    else                  msgprep_block(blockIdx.x - 625, Wup, g_sc);
}

// ---------------- layer-1 table (grid-stride) ------------------------------
__global__ __launch_bounds__(256)
void k_table(const float* __restrict__ Wr1, const float* __restrict__ br1,
             const float* __restrict__ Wr2){
    table_gs(blockIdx.x, Wr1, br1, Wr2);
}

// ---------------- gather: per-node aggregation, no atomics -----------------
__global__ __launch_bounds__(256)
void k_gather(const int* __restrict__ snd){
    int tid = threadIdx.x;
    int j = tid & 63, slot = tid >> 6;
    int n = blockIdx.x*4 + slot;           // NN == 4*2500 exactly
    int i0r = g_row[n], i1r = g_row[n+1];
    float invdt = (float)TPTS / get_lm();
    float a0 = 0.f, a1 = 0.f, a2 = 0.f, a3 = 0.f;
    for (int it = i0r; it < i1r; it++){
        int e = g_eid[it];
        float4 ed = g_edat[e];
        int s = snd[e];
        float f = ed.w * invdt;
        int i0 = (int)f;
        i0 = max(1, min(i0, TPTS-3));
        float tf = f - (float)i0;
        float tm = tf - 1.f, tp = tf + 1.f, t2 = tf - 2.f;
        float w0 = -tf*tm*t2*(1.f/6.f);
        float w1 =  tp*tm*t2*0.5f;
        float w2 = -tf*tp*t2*0.5f;
        float w3 =  tf*tp*tm*(1.f/6.f);
        const float* tb = &g_tab[(i0-1)*64 + j];
        float r = w0*tb[0] + w1*tb[64] + w2*tb[128] + w3*tb[192];
        float m = r * g_nfup0[s*64 + j];
        a0 += m;
        a1 = fmaf(m, ed.x, a1);
        a2 = fmaf(m, ed.y, a2);
        a3 = fmaf(m, ed.z, a3);
    }
    float* a = &g_agg[n*256 + j];
    a[0]   = a0;
    a[64]  = a1;
    a[128] = a2;
    a[192] = a3;
}

// ---------------- nodeA: a = agg@W_mix; nf = (a*(1+s+s^2))@W_prod ----------
__global__ __launch_bounds__(256)
void k_nodeA(const float* __restrict__ Wmix, const float* __restrict__ Wprod){
    __shared__ __align__(16) float sWmixT[64*WS];
    __shared__ __align__(16) float sWprodT[64*WS];
    __shared__ __align__(16) float4 s_in[4][64];
    __shared__ __align__(16) float s_ap[4][256];
    int tid = threadIdx.x;
    int j = tid & 63, slot = tid >> 6;
    load_wT(sWmixT, Wmix, tid);
    load_wT(sWprodT, Wprod, tid);
    __syncthreads();
    const float4* wm = (const float4*)&sWmixT[j*WS];
    const float4* wp = (const float4*)&sWprodT[j*WS];
    for (int base = blockIdx.x*4; base < NN; base += NGRID*4){
        int n = base + slot;
        s_in[slot][j] = ((const float4*)(g_agg + n*256))[j];
        __syncthreads();
        {
            float a0=0.f, a1=0.f, a2=0.f, a3=0.f;
            const float4* i4 = s_in[slot];
            #pragma unroll
            for (int q = 0; q < 16; q++){
                float4 v0 = i4[q];
                float4 v1 = i4[16+q];
                float4 v2 = i4[32+q];
                float4 v3 = i4[48+q];
                float4 w = wm[q];
                a0 = fmaf(v0.x,w.x, fmaf(v0.y,w.y, fmaf(v0.z,w.z, fmaf(v0.w,w.w, a0))));
                a1 = fmaf(v1.x,w.x, fmaf(v1.y,w.y, fmaf(v1.z,w.z, fmaf(v1.w,w.w, a1))));
                a2 = fmaf(v2.x,w.x, fmaf(v2.y,w.y, fmaf(v2.z,w.z, fmaf(v2.w,w.w, a2))));
                a3 = fmaf(v3.x,w.x, fmaf(v3.y,w.y, fmaf(v3.z,w.z, fmaf(v3.w,w.w, a3))));
            }
            float poly = 1.f + a0 + a0*a0;
            s_ap[slot][j]        = a0 * poly;
            s_ap[slot][64 + j]   = a1 * poly;
            s_ap[slot][128 + j]  = a2 * poly;
            s_ap[slot][192 + j]  = a3 * poly;
        }
        __syncthreads();
        {
            float n0=0.f, n1=0.f, n2=0.f, n3=0.f;
            const float4* p4 = (const float4*)s_ap[slot];
            #pragma unroll
            for (int q = 0; q < 16; q++){
                float4 v0 = p4[q];
                float4 v1 = p4[16+q];
                float4 v2 = p4[32+q];
                float4 v3 = p4[48+q];
                float4 w = wp[q];
                n0 = fmaf(v0.x,w.x, fmaf(v0.y,w.y, fmaf(v0.z,w.z, fmaf(v0.w,w.w, n0))));
                n1 = fmaf(v1.x,w.x, fmaf(v1.y,w.y, fmaf(v1.z,w.z, fmaf(v1.w,w.w, n1))));
                n2 = fmaf(v2.x,w.x, fmaf(v2.y,w.y, fmaf(v2.z,w.z, fmaf(v2.w,w.w, n2))));
                n3 = fmaf(v3.x,w.x, fmaf(v3.y,w.y, fmaf(v3.z,w.z, fmaf(v3.w,w.w, n3))));
            }
            g_sc[n*64 + j] = n0;
            g_v3[n*192 + j]        = n1;
            g_v3[n*192 + 64 + j]   = n2;
            g_v3[n*192 + 128 + j]  = n3;
        }
        __syncthreads();
    }
}

// ---------------- nodeB fused (B1+B2), transposed weights, ~101KB dyn smem -
// layout (floats): Wro1T[4352] | WgT[4352] | Wro2T[4352] | W2T[4352] | W1T[8448]
__global__ __launch_bounds__(256, 2)
void k_nodeB12(const float* __restrict__ Wro1, const float* __restrict__ bro1,
               const float* __restrict__ Wro2, const float* __restrict__ Wg,
               const float* __restrict__ wv,
               const float* __restrict__ W1, const float* __restrict__ b1,
               const float* __restrict__ W2, const float* __restrict__ b2){
    extern __shared__ float smemf[];
    float* sWro1T = smemf;
    float* sWgT   = smemf + 4352;
    float* sWro2T = smemf + 8704;
    float* sW2T   = smemf + 13056;
    float* sW1T   = smemf + 17408;
    __shared__ float sbro1[64], swv[64], sb1[64], sb2[64];
    __shared__ __align__(16) float s_sc[4][64];
    __shared__ __align__(16) float s_hid[4][64];
    __shared__ __align__(16) float s_in2[4][128];
    __shared__ __align__(16) float s_u[4][64];
    __shared__ float s_red[4][2][3];
    int tid = threadIdx.x;
    int j = tid & 63, slot = tid >> 6;
    int lane = tid & 31, wslot = (tid >> 5) & 1;
    if (blockIdx.x == 0 && tid == 0) g_lmax_bits = 0u;   // reset for next layer
    load_wT(sWro1T, Wro1, tid);
    load_wT(sWgT,   Wg,   tid);
    load_wT(sWro2T, Wro2, tid);
    load_wT(sW2T,   W2,   tid);
    for (int x = tid; x < 8192; x += 256){
        int m = x >> 6, jj = x & 63;
        sW1T[jj*WS1 + m] = W1[x];
    }
    if (tid < 64){ sbro1[tid] = bro1[tid]; swv[tid] = wv[tid]; sb1[tid] = b1[tid]; sb2[tid] = b2[tid]; }
    __syncthreads();
    const float4* wro1r = (const float4*)&sWro1T[j*WS];
    const float4* wgr   = (const float4*)&sWgT[j*WS];
    const float4* wro2r = (const float4*)&sWro2T[j*WS];
    const float4* w2r   = (const float4*)&sW2T[j*WS];
    const float4* w1r   = (const float4*)&sW1T[j*WS1];

    for (int base = blockIdx.x*4; base < NN; base += NBGRID*4){
        int n = base + slot;
        s_sc[slot][j] = g_sc[n*64 + j];
        __syncthreads();

        float acc1 = sbro1[j], accg = 0.f;
        {
            const float4* sc4 = (const float4*)s_sc[slot];
            #pragma unroll
            for (int q = 0; q < 16; q++){
                float4 v = sc4[q];
                float4 wa = wro1r[q];
                float4 wb = wgr[q];
                acc1 = fmaf(v.x, wa.x, acc1);
                acc1 = fmaf(v.y, wa.y, acc1);
                acc1 = fmaf(v.z, wa.z, acc1);
                acc1 = fmaf(v.w, wa.w, acc1);
                accg = fmaf(v.x, wb.x, accg);
                accg = fmaf(v.y, wb.y, accg);
                accg = fmaf(v.z, wb.z, accg);
                accg = fmaf(v.w, wb.w, accg);
            }
        }
        s_hid[slot][j] = siluf(acc1);
        float gw = siluf(accg) * swv[j];

        float p0 = gw * g_v3[n*192 +   0 + j];
        float p1 = gw * g_v3[n*192 +  64 + j];
        float p2 = gw * g_v3[n*192 + 128 + j];
        #pragma unroll
        for (int off = 16; off > 0; off >>= 1){
            p0 += __shfl_down_sync(0xffffffffu, p0, off);
            p1 += __shfl_down_sync(0xffffffffu, p1, off);
            p2 += __shfl_down_sync(0xffffffffu, p2, off);
        }
        if (lane == 0){
            s_red[slot][wslot][0] = p0;
            s_red[slot][wslot][1] = p1;
            s_red[slot][wslot][2] = p2;
        }
        __syncthreads();

        float scal = 0.f;
        {
            const float4* h4 = (const float4*)s_hid[slot];
            #pragma unroll
            for (int q = 0; q < 16; q++){
                float4 v = h4[q];
                float4 w = wro2r[q];
                scal = fmaf(v.x, w.x, scal);
                scal = fmaf(v.y, w.y, scal);
                scal = fmaf(v.z, w.z, scal);
                scal = fmaf(v.w, w.w, scal);
            }
        }
        s_in2[slot][j]      = g_h[n*64 + j];
        s_in2[slot][64 + j] = scal;
        if (j == 0){
            g_pos[n*3+0] += s_red[slot][0][0] + s_red[slot][1][0];
            g_pos[n*3+1] += s_red[slot][0][1] + s_red[slot][1][1];
            g_pos[n*3+2] += s_red[slot][0][2] + s_red[slot][1][2];
        }
        __syncthreads();

        float acc = sb1[j];
        {
            const float4* i4 = (const float4*)s_in2[slot];
            #pragma unroll
            for (int q = 0; q < 32; q++){
                float4 v = i4[q];
                float4 w = w1r[q];
                acc = fmaf(v.x, w.x, acc);
                acc = fmaf(v.y, w.y, acc);
                acc = fmaf(v.z, w.z, acc);
                acc = fmaf(v.w, w.w, acc);
            }
        }
        s_u[slot][j] = siluf(acc);
        __syncthreads();

        float ho = sb2[j] + s_in2[slot][j];
        {
            const float4* u4 = (const float4*)s_u[slot];
            #pragma unroll
            for (int q = 0; q < 16; q++){
                float4 v = u4[q];
                float4 w = w2r[q];
                ho = fmaf(v.x, w.x, ho);
                ho = fmaf(v.y, w.y, ho);
                ho = fmaf(v.z, w.z, ho);
                ho = fmaf(v.w, w.w, ho);
            }
        }
        g_h[n*64 + j] = ho;
        __syncthreads();
    }
}

// ---------------- outputs ---------------------------------------------------
__global__ void k_predbin(const float* __restrict__ W_out, const float* __restrict__ b_out,
                          const int* __restrict__ batch, float* __restrict__ out){
    int idx = blockIdx.x*blockDim.x + threadIdx.x;
    if (idx < NN){
        int b = batch[idx];
        atomicAdd(&g_bsum[b*3 + 0], g_pos[idx*3 + 0]);
        atomicAdd(&g_bsum[b*3 + 1], g_pos[idx*3 + 1]);
        atomicAdd(&g_bsum[b*3 + 2], g_pos[idx*3 + 2]);
        atomicAdd(&g_bcnt[b], 1.f);
    }
    if (idx >= NN*16) return;
    int n = idx >> 4, j = idx & 15;
    if (j >= 10) return;
    float acc = b_out[j];
    #pragma unroll
    for (int h = 0; h < 64; h++) acc += g_h[n*64 + h] * __ldg(&W_out[h*11 + j]);
    out[n*10 + j] = acc;
}

__global__ void k_posout(const int* __restrict__ batch,
                         const float* __restrict__ positions,
                         float* __restrict__ out){
    int i = blockIdx.x*blockDim.x + threadIdx.x;
    if (i >= NN*3) return;
    int n = i / 3, c = i % 3;
    int b = batch[n];
    float cnt = fmaxf(g_bcnt[b], 1.f);
    out[NN*10 + i] = g_pos[i] - g_bsum[b*3 + c] / cnt - positions[i];
}

// ---------------- launcher --------------------------------------------------
extern "C" void kernel_launch(void* const* d_in, const int* in_sizes, int n_in,
                              void* d_out, int out_size){
    const float* positions  = (const float*)d_in[0];
    const float* node_attrs = (const float*)d_in[1];
    const float* t          = (const float*)d_in[2];
    const float* shifts     = (const float*)d_in[3];
    const int*   batch      = (const int*)  d_in[4];
    const int*   eidx       = (const int*)  d_in[5];
    const float* W_emb  = (const float*)d_in[6];
    const float* b_emb  = (const float*)d_in[7];
    const float* W_out  = (const float*)d_in[8];
    const float* b_out  = (const float*)d_in[9];
    const float* Wr1    = (const float*)d_in[10];
    const float* br1    = (const float*)d_in[11];
    const float* Wr2    = (const float*)d_in[12];
    const float* W_up   = (const float*)d_in[13];
    const float* W_mix  = (const float*)d_in[14];
    const float* W_prod = (const float*)d_in[15];
    const float* Wro1   = (const float*)d_in[16];
    const float* bro1   = (const float*)d_in[17];
    const float* Wro2   = (const float*)d_in[18];
    const float* Wg     = (const float*)d_in[19];
    const float* wv     = (const float*)d_in[20];
    const float* Wmlp1  = (const float*)d_in[21];
    const float* bmlp1  = (const float*)d_in[22];
    const float* Wmlp2  = (const float*)d_in[23];
    const float* bmlp2  = (const float*)d_in[24];
    float* out = (float*)d_out;

    const int* snd = eidx;
    const int* rcv = eidx + EE;

    const int NB_SMEM = (4*4352 + 8448) * 4;   // 103424 B dynamic for k_nodeB12
    cudaFuncSetAttribute(k_nodeB12, cudaFuncAttributeMaxDynamicSharedMemorySize, NB_SMEM);

    k_inithist<<<118 + 625, 256>>>(positions, rcv);
    k_scan<<<1, 1024>>>();
    k_fillembed<<<625 + 2500 + 625, 256>>>(snd, rcv, shifts, node_attrs, t, batch,
                                           W_emb, b_emb);

    // layer 0 (geometry already done in fillembed)
    k_tabprep0<<<NGRID + NGRID, 256>>>(Wr1, br1, Wr2, W_up);
    k_gather<<<NN/4, 256>>>(snd);
    k_nodeA<<<NGRID, 256>>>(W_mix, W_prod);
    k_nodeB12<<<NBGRID, 256, NB_SMEM>>>(Wro1, bro1, Wro2, Wg, wv,
                                        Wmlp1, bmlp1, Wmlp2, bmlp2);

    // layer 1
    k_geomprep<<<625 + NGRID, 256>>>(snd, rcv, shifts, W_up + 4096);
    k_table<<<NGRID, 256>>>(Wr1 + 64, br1 + 64, Wr2 + 4096);
    k_gather<<<NN/4, 256>>>(snd);
    k_nodeA<<<NGRID, 256>>>(W_mix + 4096, W_prod + 4096);
    k_nodeB12<<<NBGRID, 256, NB_SMEM>>>(Wro1 + 4096, bro1 + 64, Wro2 + 4096,
                                        Wg + 4096, wv + 64,
                                        Wmlp1 + 8192, bmlp1 + 64,
                                        Wmlp2 + 4096, bmlp2 + 64);

    k_predbin<<<(NN*16 + 255)/256, 256>>>(W_out, b_out, batch, out);
    k_posout<<<(NN*3 + 255)/256, 256>>>(batch, positions, out);
}

// round 15
// speedup vs baseline: 1.8032x; 1.8032x over previous
#include <cuda_runtime.h>
#include <math.h>

#define NN 10000
#define EE 160000
#define BB 64
#define HH 64
#define EPSN 1e-9f
#define SQ3 1.7320508f
#define INV_AVG 0.0625f   // 1/16

#define TPTS 4096
#define TGRID (TPTS/4)     // 1024 table blocks, one 4-row chunk each
#define NGRID 592          // 4*148 blocks for grid-stride node kernels
#define NBGRID 296         // 2/SM at 80KB smem for fused nodeB

// ---------------- scratch (static device globals; no allocation) -----------
__device__ float g_h[NN*HH];
__device__ float g_nfup0[NN*HH];
__device__ float g_sc[NN*HH];
__device__ float g_v3[NN*3*HH];
__device__ float g_agg[NN*4*HH];
__device__ float g_pos[NN*3];
__device__ float g_bsum[BB*3];
__device__ float g_bcnt[BB];
__device__ float g_tab[TPTS*HH];
__device__ float4 g_edat[EE];
__device__ int   g_cnt[NN];         // zeroed by k_scan after use (self-cleaning)
__device__ int   g_row[NN+1];
__device__ int   g_cur[NN];
__device__ int   g_eid[EE];
__device__ unsigned g_lmax_bits;

__device__ __forceinline__ float siluf(float x){
    float e = __expf(-x);
    return __fdividef(x, 1.f + e);
}

__device__ __forceinline__ float get_lm(){
    return fmaxf(__uint_as_float(g_lmax_bits), 1e-3f) * 1.0001f;
}

// ---------------- device helper: per-edge geometry + lmax reduce -----------
__device__ __forceinline__ void geom_block(int gb, const int* __restrict__ snd,
                                           const int* __restrict__ rcv,
                                           const float* __restrict__ shifts){
    __shared__ float s_max[256];
    int e = gb*256 + threadIdx.x;
    float len = 0.f;
    if (e < EE){
        int s = snd[e], r = rcv[e];
        float dx = g_pos[r*3+0] - g_pos[s*3+0] + shifts[e*3+0];
        float dy = g_pos[r*3+1] - g_pos[s*3+1] + shifts[e*3+1];
        float dz = g_pos[r*3+2] - g_pos[s*3+2] + shifts[e*3+2];
        len = sqrtf(dx*dx + dy*dy + dz*dz);
        float inv = SQ3 / (len + EPSN);
        g_edat[e] = make_float4(dx*inv, dy*inv, dz*inv, len);
    }
    int tid = threadIdx.x;
    s_max[tid] = len;
    __syncthreads();
    for (int off = 128; off > 0; off >>= 1){
        if (tid < off) s_max[tid] = fmaxf(s_max[tid], s_max[tid + off]);
        __syncthreads();
    }
    if (tid == 0) atomicMax(&g_lmax_bits, __float_as_uint(s_max[0]));
}

// ---------------- device helper: table build (reg-resident Wr2 column) -----
__device__ __forceinline__ void table_gs(int bid, const float* __restrict__ Wr1,
                                         const float* __restrict__ br1,
                                         const float* __restrict__ Wr2){
    __shared__ __align__(16) float sv[4][64];
    __shared__ float w1[64], b1[64];
    int tid = threadIdx.x;
    int j = tid & 63, slot = tid >> 6;
    float wcol[64];
    #pragma unroll
    for (int k = 0; k < 64; k++) wcol[k] = __ldg(&Wr2[k*64 + j]);
    if (tid < 64){ w1[tid] = Wr1[tid]; b1[tid] = br1[tid]; }
    float dt = get_lm() / (float)TPTS;
    __syncthreads();
    for (int pb = bid*4; pb < TPTS; pb += TGRID*4){
        int p = pb + slot;
        float lp = (float)p * dt;
        sv[slot][j] = siluf(lp * w1[j] + b1[j]);
        __syncthreads();
        float acc = 0.f;
        const float4* v4 = (const float4*)sv[slot];
        #pragma unroll
        for (int q = 0; q < 16; q++){
            float4 v = v4[q];
            acc = fmaf(v.x, wcol[4*q+0], acc);
            acc = fmaf(v.y, wcol[4*q+1], acc);
            acc = fmaf(v.z, wcol[4*q+2], acc);
            acc = fmaf(v.w, wcol[4*q+3], acc);
        }
        g_tab[p*64 + j] = acc * INV_AVG;
        __syncthreads();
    }
}

// ---------------- device helper: msgprep (nfup0 = src @ W_up) --------------
__device__ __forceinline__ void msgprep_block(int bid, const float* __restrict__ Wup,
                                              const float* __restrict__ src){
    __shared__ __align__(16) float srow[4][64];
    int tid = threadIdx.x;
    int j = tid & 63, slot = tid >> 6;
    float wcol[64];
    #pragma unroll
    for (int k = 0; k < 64; k++) wcol[k] = __ldg(&Wup[k*64 + j]);
    for (int base = bid*4; base < NN; base += NGRID*4){
        int n = base + slot;
        srow[slot][j] = src[n*64 + j];
        __syncthreads();
        float acc = 0.f;
        const float4* r4 = (const float4*)srow[slot];
        #pragma unroll
        for (int q = 0; q < 16; q++){
            float4 v = r4[q];
            acc = fmaf(v.x, wcol[4*q+0], acc);
            acc = fmaf(v.y, wcol[4*q+1], acc);
            acc = fmaf(v.z, wcol[4*q+2], acc);
            acc = fmaf(v.w, wcol[4*q+3], acc);
        }
        g_nfup0[n*64 + j] = acc;
        __syncthreads();
    }
}

// ---------------- init + hist merged (g_cnt NOT zeroed here: see k_scan) ---
__global__ void k_inithist(const float* __restrict__ positions,
                           const int* __restrict__ rcv){
    if (blockIdx.x < 118){
        int i = blockIdx.x*256 + threadIdx.x;
        if (i < NN*3) g_pos[i] = positions[i];
        if (i < BB*3) g_bsum[i] = 0.f;
        if (i < BB)   g_bcnt[i] = 0.f;
        if (i == 0)   g_lmax_bits = 0u;
    } else {
        int e = (blockIdx.x - 118)*256 + threadIdx.x;
        if (e < EE) atomicAdd(&g_cnt[rcv[e]], 1);
    }
}

// scan consumes g_cnt and re-zeroes it for the next launch (graph replay).
__global__ void k_scan(){   // single block, 1024 threads
    __shared__ int s_part[1024];
    int tid = threadIdx.x;
    const int CH = (NN + 1023) / 1024;    // 10
    int base = tid * CH;
    int cnts[CH];
    int sum = 0;
    #pragma unroll
    for (int k = 0; k < CH; k++){
        int i = base + k;
        if (i < NN){
            cnts[k] = g_cnt[i];
            g_cnt[i] = 0;                 // self-clean (each i owned by 1 thread)
            sum += cnts[k];
        } else cnts[k] = 0;
    }
    s_part[tid] = sum;
    __syncthreads();
    for (int off = 1; off < 1024; off <<= 1){
        int v = s_part[tid];
        int add = (tid >= off) ? s_part[tid - off] : 0;
        __syncthreads();
        s_part[tid] = v + add;
        __syncthreads();
    }
    int excl = (tid == 0) ? 0 : s_part[tid - 1];
    #pragma unroll
    for (int k = 0; k < CH; k++){
        int i = base + k;
        if (i < NN){
            g_row[i] = excl;
            g_cur[i] = excl;
            excl += cnts[k];
        }
    }
    if (tid == 1023) g_row[NN] = EE;
}

// ---------------- fill + embed + layer-0 geometry, merged ------------------
// blocks 0..624 fill | 625..3124 embed | 3125..3749 geom(layer 0)
__global__ void k_fillembed(const int* __restrict__ snd, const int* __restrict__ rcv,
                            const float* __restrict__ shifts,
                            const float* __restrict__ node_attrs,
                            const float* __restrict__ t,
                            const int* __restrict__ batch,
                            const float* __restrict__ W_emb,
                            const float* __restrict__ b_emb){
    if (blockIdx.x < 625){
        int e = blockIdx.x*256 + threadIdx.x;
        if (e < EE){
            int pos = atomicAdd(&g_cur[rcv[e]], 1);
            g_eid[pos] = e;
        }
    } else if (blockIdx.x < 3125){
        int idx = (blockIdx.x - 625)*256 + threadIdx.x;
        if (idx >= NN*HH) return;
        int n = idx >> 6, j = idx & 63;
        float acc = b_emb[j];
        #pragma unroll
        for (int f = 0; f < 10; f++)
            acc += (node_attrs[n*10 + f] * 0.25f) * W_emb[f*64 + j];
        acc += t[batch[n]] * W_emb[10*64 + j];
        g_h[idx] = acc;
    } else {
        geom_block(blockIdx.x - 3125, snd, rcv, shifts);
    }
}

// ---------------- layer-0: table(gs) + msgprep merged ----------------------
// blocks 0..TGRID-1 table | TGRID..TGRID+NGRID-1 msgprep (src = g_h)
__global__ __launch_bounds__(256)
void k_tabprep0(const float* __restrict__ Wr1, const float* __restrict__ br1,
                const float* __restrict__ Wr2, const float* __restrict__ Wup){
    if (blockIdx.x < TGRID) table_gs(blockIdx.x, Wr1, br1, Wr2);
    else                    msgprep_block(blockIdx.x - TGRID, Wup, g_h);
}

// ---------------- layer-1: geom + msgprep merged (src = g_sc) --------------
__global__ __launch_bounds__(256)
void k_geomprep(const int* __restrict__ snd, const int* __restrict__ rcv,
                const float* __restrict__ shifts, const float* __restrict__ Wup){
    if (blockIdx.x < 625) geom_block(blockIdx.x, snd, rcv, shifts);
    else                  msgprep_block(blockIdx.x - 625, Wup, g_sc);
}

// ---------------- layer-1 table --------------------------------------------
__global__ __launch_bounds__(256)
void k_table(const float* __restrict__ Wr1, const float* __restrict__ br1,
             const float* __restrict__ Wr2){
    table_gs(blockIdx.x, Wr1, br1, Wr2);
}

// ---------------- gather: per-node aggregation, no atomics -----------------
__global__ __launch_bounds__(256)
void k_gather(const int* __restrict__ snd){
    int tid = threadIdx.x;
    int j = tid & 63, slot = tid >> 6;
    int n = blockIdx.x*4 + slot;           // NN == 4*2500 exactly
    int i0r = g_row[n], i1r = g_row[n+1];
    float invdt = (float)TPTS / get_lm();
    float a0 = 0.f, a1 = 0.f, a2 = 0.f, a3 = 0.f;
    for (int it = i0r; it < i1r; it++){
        int e = g_eid[it];
        float4 ed = g_edat[e];
        int s = snd[e];
        float f = ed.w * invdt;            // guaranteed in [0, TPTS]
        int i0 = (int)f;
        i0 = max(1, min(i0, TPTS-3));
        float tf = f - (float)i0;          // bounded
        float tm = tf - 1.f, tp = tf + 1.f, t2 = tf - 2.f;
        float w0 = -tf*tm*t2*(1.f/6.f);
        float w1 =  tp*tm*t2*0.5f;
        float w2 = -tf*tp*t2*0.5f;
        float w3 =  tf*tp*tm*(1.f/6.f);
        const float* tb = &g_tab[(i0-1)*64 + j];
        float r = w0*tb[0] + w1*tb[64] + w2*tb[128] + w3*tb[192];
        float m = r * g_nfup0[s*64 + j];
        a0 += m;
        a1 = fmaf(m, ed.x, a1);
        a2 = fmaf(m, ed.y, a2);
        a3 = fmaf(m, ed.z, a3);
    }
    float* a = &g_agg[n*256 + j];
    a[0]   = a0;
    a[64]  = a1;
    a[128] = a2;
    a[192] = a3;
}

// ---------------- nodeA: a = agg@W_mix; nf = (a*(1+s+s^2))@W_prod ----------
__global__ __launch_bounds__(256)
void k_nodeA(const float* __restrict__ Wmix, const float* __restrict__ Wprod){
    __shared__ float sWprod[4096];
    __shared__ __align__(16) float4 s_in[4][64];     // [slot][l*16+q]
    __shared__ __align__(16) float s_ap[4][256];
    int tid = threadIdx.x;
    int j = tid & 63, slot = tid >> 6;
    float wmixc[64];
    #pragma unroll
    for (int k = 0; k < 64; k++) wmixc[k] = __ldg(&Wmix[k*64 + j]);
    for (int x = tid; x < 4096; x += 256) sWprod[x] = Wprod[x];
    for (int base = blockIdx.x*4; base < NN; base += NGRID*4){
        int n = base + slot;
        s_in[slot][j] = ((const float4*)(g_agg + n*256))[j];
        __syncthreads();
        float a0=0.f, a1=0.f, a2=0.f, a3=0.f;
        {
            const float4* i4 = s_in[slot];
            #pragma unroll
            for (int q = 0; q < 16; q++){
                float4 v0 = i4[q];
                float4 v1 = i4[16+q];
                float4 v2 = i4[32+q];
                float4 v3 = i4[48+q];
                float w0 = wmixc[4*q+0], w1 = wmixc[4*q+1], w2 = wmixc[4*q+2], w3 = wmixc[4*q+3];
                a0 = fmaf(v0.x,w0, fmaf(v0.y,w1, fmaf(v0.z,w2, fmaf(v0.w,w3, a0))));
                a1 = fmaf(v1.x,w0, fmaf(v1.y,w1, fmaf(v1.z,w2, fmaf(v1.w,w3, a1))));
                a2 = fmaf(v2.x,w0, fmaf(v2.y,w1, fmaf(v2.z,w2, fmaf(v2.w,w3, a2))));
                a3 = fmaf(v3.x,w0, fmaf(v3.y,w1, fmaf(v3.z,w2, fmaf(v3.w,w3, a3))));
            }
            float poly = 1.f + a0 + a0*a0;
            s_ap[slot][j]        = a0 * poly;
            s_ap[slot][64 + j]   = a1 * poly;
            s_ap[slot][128 + j]  = a2 * poly;
            s_ap[slot][192 + j]  = a3 * poly;
        }
        __syncthreads();
        {
            float n0=0.f, n1=0.f, n2=0.f, n3=0.f;
            const float4* p4 = (const float4*)s_ap[slot];
            #pragma unroll
            for (int q = 0; q < 16; q++){
                float4 v0 = p4[q];
                float4 v1 = p4[16+q];
                float4 v2 = p4[32+q];
                float4 v3 = p4[48+q];
                float w0 = sWprod[(4*q+0)*64 + j];
                float w1 = sWprod[(4*q+1)*64 + j];
                float w2 = sWprod[(4*q+2)*64 + j];
                float w3 = sWprod[(4*q+3)*64 + j];
                n0 = fmaf(v0.x,w0, fmaf(v0.y,w1, fmaf(v0.z,w2, fmaf(v0.w,w3, n0))));
                n1 = fmaf(v1.x,w0, fmaf(v1.y,w1, fmaf(v1.z,w2, fmaf(v1.w,w3, n1))));
                n2 = fmaf(v2.x,w0, fmaf(v2.y,w1, fmaf(v2.z,w2, fmaf(v2.w,w3, n2))));
                n3 = fmaf(v3.x,w0, fmaf(v3.y,w1, fmaf(v3.z,w2, fmaf(v3.w,w3, n3))));
            }
            g_sc[n*64 + j] = n0;
            g_v3[n*192 + j]        = n1;
            g_v3[n*192 + 64 + j]   = n2;
            g_v3[n*192 + 128 + j]  = n3;
        }
        __syncthreads();
    }
}

// ---------------- nodeB fused (B1+B2), grid-stride, 80KB dynamic smem ------
__global__ __launch_bounds__(256, 2)
void k_nodeB12(const float* __restrict__ Wro1, const float* __restrict__ bro1,
               const float* __restrict__ Wro2, const float* __restrict__ Wg,
               const float* __restrict__ wv,
               const float* __restrict__ W1, const float* __restrict__ b1,
               const float* __restrict__ W2, const float* __restrict__ b2){
    extern __shared__ float smemf[];
    float* sWg   = smemf;
    float* sWro2 = smemf + 4096;
    float* sW1   = smemf + 8192;
    float* sW2   = smemf + 16384;
    __shared__ float sbro1[64], swv[64], sb1[64], sb2[64];
    __shared__ __align__(16) float s_sc[4][64];
    __shared__ __align__(16) float s_hid[4][64];
    __shared__ __align__(16) float s_in2[4][128];
    __shared__ __align__(16) float s_u[4][64];
    __shared__ float s_red[4][2][3];
    int tid = threadIdx.x;
    int j = tid & 63, slot = tid >> 6;
    int lane = tid & 31, wslot = (tid >> 5) & 1;
    if (blockIdx.x == 0 && tid == 0) g_lmax_bits = 0u;   // reset for next layer
    float wro1c[64];
    #pragma unroll
    for (int k = 0; k < 64; k++) wro1c[k] = __ldg(&Wro1[k*64 + j]);
    for (int x = tid; x < 4096; x += 256){ sWg[x] = Wg[x]; sWro2[x] = Wro2[x]; sW2[x] = W2[x]; }
    for (int x = tid; x < 8192; x += 256) sW1[x] = W1[x];
    if (tid < 64){ sbro1[tid] = bro1[tid]; swv[tid] = wv[tid]; sb1[tid] = b1[tid]; sb2[tid] = b2[tid]; }
    __syncthreads();

    for (int base = blockIdx.x*4; base < NN; base += NBGRID*4){
        int n = base + slot;
        s_sc[slot][j] = g_sc[n*64 + j];
        __syncthreads();

        float acc1 = sbro1[j], accg = 0.f;
        {
            const float4* sc4 = (const float4*)s_sc[slot];
            #pragma unroll
            for (int q = 0; q < 16; q++){
                float4 v = sc4[q];
                acc1 = fmaf(v.x, wro1c[4*q+0], acc1);
                acc1 = fmaf(v.y, wro1c[4*q+1], acc1);
                acc1 = fmaf(v.z, wro1c[4*q+2], acc1);
                acc1 = fmaf(v.w, wro1c[4*q+3], acc1);
                accg = fmaf(v.x, sWg[(4*q+0)*64 + j], accg);
                accg = fmaf(v.y, sWg[(4*q+1)*64 + j], accg);
                accg = fmaf(v.z, sWg[(4*q+2)*64 + j], accg);
                accg = fmaf(v.w, sWg[(4*q+3)*64 + j], accg);
            }
        }
        s_hid[slot][j] = siluf(acc1);
        float gw = siluf(accg) * swv[j];

        float p0 = gw * g_v3[n*192 +   0 + j];
        float p1 = gw * g_v3[n*192 +  64 + j];
        float p2 = gw * g_v3[n*192 + 128 + j];
        #pragma unroll
        for (int off = 16; off > 0; off >>= 1){
            p0 += __shfl_down_sync(0xffffffffu, p0, off);
            p1 += __shfl_down_sync(0xffffffffu, p1, off);
            p2 += __shfl_down_sync(0xffffffffu, p2, off);
        }
        if (lane == 0){
            s_red[slot][wslot][0] = p0;
            s_red[slot][wslot][1] = p1;
            s_red[slot][wslot][2] = p2;
        }
        __syncthreads();

        float scal = 0.f;
        {
            const float4* h4 = (const float4*)s_hid[slot];
            #pragma unroll
            for (int q = 0; q < 16; q++){
                float4 v = h4[q];
                scal = fmaf(v.x, sWro2[(4*q+0)*64 + j], scal);
                scal = fmaf(v.y, sWro2[(4*q+1)*64 + j], scal);
                scal = fmaf(v.z, sWro2[(4*q+2)*64 + j], scal);
                scal = fmaf(v.w, sWro2[(4*q+3)*64 + j], scal);
            }
        }
        s_in2[slot][j]      = g_h[n*64 + j];
        s_in2[slot][64 + j] = scal;
        if (j == 0){
            g_pos[n*3+0] += s_red[slot][0][0] + s_red[slot][1][0];
            g_pos[n*3+1] += s_red[slot][0][1] + s_red[slot][1][1];
            g_pos[n*3+2] += s_red[slot][0][2] + s_red[slot][1][2];
        }
        __syncthreads();

        float acc = sb1[j];
        {
            const float4* i4 = (const float4*)s_in2[slot];
            #pragma unroll
            for (int q = 0; q < 32; q++){
                float4 v = i4[q];
                acc = fmaf(v.x, sW1[(4*q+0)*64 + j], acc);
                acc = fmaf(v.y, sW1[(4*q+1)*64 + j], acc);
                acc = fmaf(v.z, sW1[(4*q+2)*64 + j], acc);
                acc = fmaf(v.w, sW1[(4*q+3)*64 + j], acc);
            }
        }
        s_u[slot][j] = siluf(acc);
        __syncthreads();

        float ho = sb2[j] + s_in2[slot][j];
        {
            const float4* u4 = (const float4*)s_u[slot];
            #pragma unroll
            for (int q = 0; q < 16; q++){
                float4 v = u4[q];
                ho = fmaf(v.x, sW2[(4*q+0)*64 + j], ho);
                ho = fmaf(v.y, sW2[(4*q+1)*64 + j], ho);
                ho = fmaf(v.z, sW2[(4*q+2)*64 + j], ho);
                ho = fmaf(v.w, sW2[(4*q+3)*64 + j], ho);
            }
        }
        g_h[n*64 + j] = ho;
        __syncthreads();
    }
}

// ---------------- outputs ---------------------------------------------------
__global__ void k_predbin(const float* __restrict__ W_out, const float* __restrict__ b_out,
                          const int* __restrict__ batch, float* __restrict__ out){
    int idx = blockIdx.x*blockDim.x + threadIdx.x;
    if (idx < NN){
        int b = batch[idx];
        atomicAdd(&g_bsum[b*3 + 0], g_pos[idx*3 + 0]);
        atomicAdd(&g_bsum[b*3 + 1], g_pos[idx*3 + 1]);
        atomicAdd(&g_bsum[b*3 + 2], g_pos[idx*3 + 2]);
        atomicAdd(&g_bcnt[b], 1.f);
    }
    if (idx >= NN*16) return;
    int n = idx >> 4, j = idx & 15;
    if (j >= 10) return;
    float acc = b_out[j];
    #pragma unroll
    for (int h = 0; h < 64; h++) acc += g_h[n*64 + h] * __ldg(&W_out[h*11 + j]);
    out[n*10 + j] = acc;
}

__global__ void k_posout(const int* __restrict__ batch,
                         const float* __restrict__ positions,
                         float* __restrict__ out){
    int i = blockIdx.x*blockDim.x + threadIdx.x;
    if (i >= NN*3) return;
    int n = i / 3, c = i % 3;
    int b = batch[n];
    float cnt = fmaxf(g_bcnt[b], 1.f);
    out[NN*10 + i] = g_pos[i] - g_bsum[b*3 + c] / cnt - positions[i];
}

// ---------------- launcher --------------------------------------------------
extern "C" void kernel_launch(void* const* d_in, const int* in_sizes, int n_in,
                              void* d_out, int out_size){
    const float* positions  = (const float*)d_in[0];
    const float* node_attrs = (const float*)d_in[1];
    const float* t          = (const float*)d_in[2];
    const float* shifts     = (const float*)d_in[3];
    const int*   batch      = (const int*)  d_in[4];
    const int*   eidx       = (const int*)  d_in[5];
    const float* W_emb  = (const float*)d_in[6];
    const float* b_emb  = (const float*)d_in[7];
    const float* W_out  = (const float*)d_in[8];
    const float* b_out  = (const float*)d_in[9];
    const float* Wr1    = (const float*)d_in[10];
    const float* br1    = (const float*)d_in[11];
    const float* Wr2    = (const float*)d_in[12];
    const float* W_up   = (const float*)d_in[13];
    const float* W_mix  = (const float*)d_in[14];
    const float* W_prod = (const float*)d_in[15];
    const float* Wro1   = (const float*)d_in[16];
    const float* bro1   = (const float*)d_in[17];
    const float* Wro2   = (const float*)d_in[18];
    const float* Wg     = (const float*)d_in[19];
    const float* wv     = (const float*)d_in[20];
    const float* Wmlp1  = (const float*)d_in[21];
    const float* bmlp1  = (const float*)d_in[22];
    const float* Wmlp2  = (const float*)d_in[23];
    const float* bmlp2  = (const float*)d_in[24];
    float* out = (float*)d_out;

    const int* snd = eidx;
    const int* rcv = eidx + EE;

    const int NB_SMEM = 20480 * 4;   // 80KB dynamic for k_nodeB12
    cudaFuncSetAttribute(k_nodeB12, cudaFuncAttributeMaxDynamicSharedMemorySize, NB_SMEM);

    k_inithist<<<118 + 625, 256>>>(positions, rcv);
    k_scan<<<1, 1024>>>();
    k_fillembed<<<625 + 2500 + 625, 256>>>(snd, rcv, shifts, node_attrs, t, batch,
                                           W_emb, b_emb);

    // layer 0 (geometry already done in fillembed)
    k_tabprep0<<<TGRID + NGRID, 256>>>(Wr1, br1, Wr2, W_up);
    k_gather<<<NN/4, 256>>>(snd);
    k_nodeA<<<NGRID, 256>>>(W_mix, W_prod);
    k_nodeB12<<<NBGRID, 256, NB_SMEM>>>(Wro1, bro1, Wro2, Wg, wv,
                                        Wmlp1, bmlp1, Wmlp2, bmlp2);

    // layer 1
    k_geomprep<<<625 + NGRID, 256>>>(snd, rcv, shifts, W_up + 4096);
    k_table<<<TGRID, 256>>>(Wr1 + 64, br1 + 64, Wr2 + 4096);
    k_gather<<<NN/4, 256>>>(snd);
    k_nodeA<<<NGRID, 256>>>(W_mix + 4096, W_prod + 4096);
    k_nodeB12<<<NBGRID, 256, NB_SMEM>>>(Wro1 + 4096, bro1 + 64, Wro2 + 4096,
                                        Wg + 4096, wv + 64,
                                        Wmlp1 + 8192, bmlp1 + 64,
                                        Wmlp2 + 4096, bmlp2 + 64);

    k_predbin<<<(NN*16 + 255)/256, 256>>>(W_out, b_out, batch, out);
    k_posout<<<(NN*3 + 255)/256, 256>>>(batch, positions, out);
}